// round 13
// baseline (speedup 1.0000x reference)
#include <cuda_runtime.h>
#include <cuda_bf16.h>
#include <cstdint>

#define BATCHN 512
#define DIM    512
#define NCLS   1000
#define MEMSZ  200
#define KPOS   50
#define KNEG   20
#define INV_TEMP (1.0f/0.07f)
#define MARGIN 0.5f

#define NMEM  (NCLS*KNEG)        // 20000 neg rows (c,k)
#define NTOT  (NMEM + BATCHN)    // 20512 (+ f rows)
#define NPAD  20608              // 161 * 128
#define NGEMM 644                // 161 ntiles * 4 mtiles
#define NBLK  (NGEMM + BATCHN)   // 1156 total k_gemm blocks

// ---------------- GEMM config (MT=128, NT=128 best known) ----------------
#define MT 128
#define NT 128
#define KT 64
#define NSTAGE 3
#define SMEM_A_BYTES (MT*KT*2)   // 16384
#define SMEM_B_BYTES (NT*KT*2)   // 16384
#define SMEM_TOTAL (NSTAGE*(SMEM_A_BYTES+SMEM_B_BYTES))  // 98304

// ---------------- device scratch (no runtime alloc allowed) ----------------
__device__ __align__(256) float         g_fnorm[BATCHN*DIM];      // normalized f (fp32)
__device__ __align__(256) __nv_bfloat16 g_fb[BATCHN*DIM];         // normalized f (bf16)
__device__ __align__(256) __nv_bfloat16 g_bmat[(size_t)NPAD*DIM]; // packed B matrix (bf16) ~21MB
__device__ int   g_rank[BATCHN], g_gsz[BATCHN], g_fi[BATCHN];
// override table: 0 = none, else sample_idx+1. Statically zero-initialized;
// the combine (last k_gemm block) resets the <=512 touched entries (replay safe).
__device__ int   g_ov[NCLS*64];
// own-class sims, TRANSPOSED layout: g_own[k*BATCHN + sample] (coalesced combine reads)
__device__ float g_own[64*BATCHN];
__device__ float g_all[BATCHN], g_hsum[BATCHN], g_hcnt[BATCHN];
__device__ float g_pbsum[BATCHN], g_pbcnt[BATCHN];
// last-block-done ticket (zero-init; reset by combine block each run)
__device__ unsigned int g_cnt;

// ================= K1: L2-normalize features + (block 512) label stats/override =================
__global__ void k_norm(const float* __restrict__ feat,
                       const int* __restrict__ labels,
                       const int* __restrict__ memptr)
{
    int i = blockIdx.x;                // 0..511 norm rows, 512 = setup block
    int t = threadIdx.x;               // 512 threads

    if (i == BATCHN) {
        // ---- setup block: label stats + override table + zero accumulators ----
        __shared__ int sl[BATCHN];
        sl[t] = labels[t];
        g_all[t] = 0.f; g_hsum[t] = 0.f; g_hcnt[t] = 0.f;
        g_pbsum[t] = 0.f; g_pbcnt[t] = 0.f;
        __syncthreads();

        int lab = sl[t];
        int r = 0, g = 0, first = -1;
        #pragma unroll 8
        for (int j = 0; j < BATCHN; j++) {
            bool s = (sl[j] == lab);
            g += s;
            r += (s && j < t);
            if (s && first < 0) first = j;
        }
        g_rank[t] = r; g_gsz[t] = g; g_fi[t] = first;

        int wp = (memptr[lab] + r) % MEMSZ;
        if (wp < 64) g_ov[lab*64 + wp] = t + 1;   // +1 encoding, 0 = none
        return;
    }

    // ---- normalization: one element per thread ----
    __shared__ float red[16];
    float v = feat[(size_t)i*DIM + t];
    float s = v*v;
    for (int o = 16; o; o >>= 1) s += __shfl_xor_sync(0xffffffffu, s, o);
    if ((t & 31) == 0) red[t >> 5] = s;
    __syncthreads();
    float tot = 0.f;
    #pragma unroll
    for (int w = 0; w < 16; w++) tot += red[w];
    float inv = 1.0f / fmaxf(sqrtf(tot), 1e-12f);
    float nv = v * inv;
    g_fnorm[(size_t)i*DIM + t] = nv;
    g_fb[(size_t)i*DIM + t]    = __float2bfloat16(nv);
}

// ================= K2: materialize packed bf16 B matrix (vectorized) =================
// 4 rows per block; 64 threads per row; each thread: 8 floats -> one 16B store
__global__ void k_bmat(const float* __restrict__ bank)
{
    int t  = threadIdx.x;              // 256
    int lr = t >> 6, l = t & 63;
    int r  = blockIdx.x*4 + lr;        // NPAD/4 blocks

    const float* src = nullptr;
    if (r < NMEM) {
        int c = r / KNEG, k = r - c*KNEG;
        int o = g_ov[c*64 + k];
        src = (o > 0) ? (g_fnorm + (size_t)(o - 1)*DIM)
                      : (bank + ((size_t)c*MEMSZ + k)*DIM);
    } else if (r < NTOT) {
        src = g_fnorm + (size_t)(r - NMEM)*DIM;
    }

    float4 v0, v1;
    if (src) {
        v0 = ((const float4*)src)[2*l];
        v1 = ((const float4*)src)[2*l + 1];
    } else {
        v0 = make_float4(0.f,0.f,0.f,0.f);
        v1 = v0;
    }
    __nv_bfloat162 b0 = __floats2bfloat162_rn(v0.x, v0.y);
    __nv_bfloat162 b1 = __floats2bfloat162_rn(v0.z, v0.w);
    __nv_bfloat162 b2 = __floats2bfloat162_rn(v1.x, v1.y);
    __nv_bfloat162 b3 = __floats2bfloat162_rn(v1.z, v1.w);
    uint4 pack;
    pack.x = *(const uint32_t*)&b0;
    pack.y = *(const uint32_t*)&b1;
    pack.z = *(const uint32_t*)&b2;
    pack.w = *(const uint32_t*)&b3;
    ((uint4*)(g_bmat + (size_t)r*DIM))[l] = pack;
}

// ================= K3: GEMM + reductions + GEMV tail + last-block combine =================
__device__ __forceinline__ void mma_bf16(float c[4], const uint32_t a[4], uint32_t b0, uint32_t b1)
{
    asm volatile(
        "mma.sync.aligned.m16n8k16.row.col.f32.bf16.bf16.f32 "
        "{%0,%1,%2,%3},{%4,%5,%6,%7},{%8,%9},{%0,%1,%2,%3};"
        : "+f"(c[0]), "+f"(c[1]), "+f"(c[2]), "+f"(c[3])
        : "r"(a[0]), "r"(a[1]), "r"(a[2]), "r"(a[3]), "r"(b0), "r"(b1));
}

extern "C" __global__ void __launch_bounds__(256, 2)
k_gemm(const int* __restrict__ labels, const float* __restrict__ bank,
       float* __restrict__ out, const int* __restrict__ memptr)
{
    extern __shared__ char smem[];
    const int bid = blockIdx.x;

    if (bid >= NGEMM) {
        // ---------- own-GEMV tail blocks: bid in [NGEMM, NBLK) ----------
        int i = bid - NGEMM;              // 0..511
        int t = threadIdx.x;              // 256
        float4* fsh = (float4*)smem;      // 2 KB scratch
        for (int j = t; j < DIM/4; j += 256)
            fsh[j] = ((const float4*)(g_fnorm + (size_t)i*DIM))[j];
        __syncthreads();
        int lab = labels[i];
        int w = t >> 5, lane = t & 31;    // 8 warps
        for (int k = KNEG + w; k < KPOS; k += 8) {
            int o = g_ov[lab*64 + k];
            const float4* row = (const float4*)((o > 0)
                ? (g_fnorm + (size_t)(o - 1)*DIM)
                : (bank + ((size_t)lab*MEMSZ + k)*DIM));
            float s = 0.f;
            #pragma unroll
            for (int c = 0; c < 4; c++) {
                float4 a = row[lane + c*32], b = fsh[lane + c*32];
                s += a.x*b.x + a.y*b.y + a.z*b.z + a.w*b.w;
            }
            for (int off = 16; off; off >>= 1) s += __shfl_xor_sync(0xffffffffu, s, off);
            if (lane == 0) g_own[k*BATCHN + i] = s * INV_TEMP;
        }
    } else {
        // ---------- GEMM blocks: bid = ntile*4 + mtile (mtile-adjacent for L2 reuse) ----------
        uint32_t saA = (uint32_t)__cvta_generic_to_shared(smem);
        uint32_t saB = saA + NSTAGE*SMEM_A_BYTES;

        const int t     = threadIdx.x;    // 256
        const int ntile = bid >> 2;       // 161
        const int mtile = bid & 3;        // 4
        const int mbase = mtile*MT, nbase = ntile*NT;
        const int wid = t >> 5, lane = t & 31;
        const int wm = wid >> 1, wn = wid & 1;  // 4 x 2 warp grid, warp tile 32x64

        auto loadA = [&](int stage, int kbase) {
            #pragma unroll
            for (int i = 0; i < 4; i++) {
                int idx = t + i*256;
                int row = idx >> 3, cc = idx & 7;
                const void* g = g_fb + (size_t)(mbase + row)*DIM + kbase + cc*8;
                uint32_t d = saA + stage*SMEM_A_BYTES + row*128 + ((cc*16) ^ ((row & 7) << 4));
                asm volatile("cp.async.cg.shared.global [%0], [%1], 16;" :: "r"(d), "l"(g));
            }
        };
        auto loadB = [&](int stage, int kbase) {
            #pragma unroll
            for (int i = 0; i < 4; i++) {
                int idx = t + i*256;
                int row = idx >> 3, cc = idx & 7;
                const void* g = g_bmat + (size_t)(nbase + row)*DIM + kbase + cc*8;
                uint32_t d = saB + stage*SMEM_B_BYTES + row*128 + ((cc*16) ^ ((row & 7) << 4));
                asm volatile("cp.async.cg.shared.global [%0], [%1], 16;" :: "r"(d), "l"(g));
            }
        };

        float acc[2][8][4];
        #pragma unroll
        for (int a = 0; a < 2; a++)
            #pragma unroll
            for (int b = 0; b < 8; b++)
                #pragma unroll
                for (int c = 0; c < 4; c++) acc[a][b][c] = 0.f;

        loadA(0, 0);  loadB(0, 0);  asm volatile("cp.async.commit_group;" ::: "memory");
        loadA(1, KT); loadB(1, KT); asm volatile("cp.async.commit_group;" ::: "memory");

        const int a_row  = wm*32 + (lane & 15);
        const int a_xor  = (a_row & 7) << 4;
        const int a_c8b  = ((lane >> 4) & 1) * 16;
        const int b_rin  = (lane & 7) + (((lane >> 4) & 1) << 3);
        const int b_c8b  = ((lane >> 3) & 1) * 16;

        const int NS = DIM / KT;  // 8
        for (int ks = 0; ks < NS; ks++) {
            if (ks < NS - 1) asm volatile("cp.async.wait_group 1;" ::: "memory");
            else             asm volatile("cp.async.wait_group 0;" ::: "memory");
            __syncthreads();

            if (ks + 2 < NS) {
                int st = (ks + 2) % NSTAGE;
                loadA(st, (ks + 2)*KT); loadB(st, (ks + 2)*KT);
                asm volatile("cp.async.commit_group;" ::: "memory");
            }

            uint32_t sa = saA + (ks % NSTAGE)*SMEM_A_BYTES;
            uint32_t sb = saB + (ks % NSTAGE)*SMEM_B_BYTES;

            #pragma unroll
            for (int kk = 0; kk < 4; kk++) {
                uint32_t afr[2][4];
                uint32_t bfr[4][4];
                #pragma unroll
                for (int mi = 0; mi < 2; mi++) {
                    uint32_t addr = sa + (a_row + mi*16)*128 + ((kk*32 + a_c8b) ^ a_xor);
                    asm volatile("ldmatrix.sync.aligned.m8n8.x4.shared.b16 {%0,%1,%2,%3}, [%4];"
                        : "=r"(afr[mi][0]), "=r"(afr[mi][1]), "=r"(afr[mi][2]), "=r"(afr[mi][3])
                        : "r"(addr));
                }
                #pragma unroll
                for (int np = 0; np < 4; np++) {
                    int nrow = wn*64 + np*16 + b_rin;
                    uint32_t baddr = sb + nrow*128 + ((kk*32 + b_c8b) ^ ((nrow & 7) << 4));
                    asm volatile("ldmatrix.sync.aligned.m8n8.x4.shared.b16 {%0,%1,%2,%3}, [%4];"
                        : "=r"(bfr[np][0]), "=r"(bfr[np][1]), "=r"(bfr[np][2]), "=r"(bfr[np][3])
                        : "r"(baddr));
                }
                #pragma unroll
                for (int np = 0; np < 4; np++) {
                    #pragma unroll
                    for (int mi = 0; mi < 2; mi++) {
                        mma_bf16(acc[mi][2*np],   afr[mi], bfr[np][0], bfr[np][1]);
                        mma_bf16(acc[mi][2*np+1], afr[mi], bfr[np][2], bfr[np][3]);
                    }
                }
            }
        }

        // ---------------- fused epilogue ----------------
        const int gid = lane >> 2, tq = lane & 3;
        int rows[4]; int lab[4]; int fi_[4]; int gsz_[4];
        #pragma unroll
        for (int mi = 0; mi < 2; mi++) {
            int r0 = mbase + wm*32 + mi*16 + gid;
            rows[2*mi] = r0; rows[2*mi+1] = r0 + 8;
        }
        #pragma unroll
        for (int q = 0; q < 4; q++) {
            lab[q]  = labels[rows[q]];
            fi_[q]  = g_fi[rows[q]];
            gsz_[q] = g_gsz[rows[q]];
        }

        float lAll[4] = {0,0,0,0}, lHS[4] = {0,0,0,0}, lHC[4] = {0,0,0,0};
        float lPS[4] = {0,0,0,0}, lPC[4] = {0,0,0,0};

        #pragma unroll
        for (int nf = 0; nf < 8; nf++) {
            int ncol0 = nbase + wn*64 + nf*8 + tq*2;
            #pragma unroll
            for (int cc = 0; cc < 2; cc++) {
                int r = ncol0 + cc;
                int type, cC = 0, kK = 0, lj = 0, rj = 0;
                if (r < NMEM)      { type = 0; cC = r / KNEG; kK = r - cC*KNEG; }
                else if (r < NTOT) { type = 1; int j = r - NMEM; lj = labels[j]; rj = g_rank[j]; }
                else               { type = 2; }
                #pragma unroll
                for (int q = 0; q < 4; q++) {
                    float s = acc[q >> 1][nf][(q & 1)*2 + cc] * INV_TEMP;
                    if (type == 0) {
                        if (cC == lab[q]) {
                            g_own[kK*BATCHN + rows[q]] = s;  // unique writer, covers all k<20
                        } else {
                            lAll[q] += s;
                            if (s > MARGIN) { lHS[q] += s; lHC[q] += 1.f; }
                        }
                    } else if (type == 1) {
                        if (lj == lab[q] && rj != fi_[q] && gsz_[q] > 1) {
                            lPS[q] += s; lPC[q] += 1.f;
                        }
                    }
                }
            }
        }

        #pragma unroll
        for (int q = 0; q < 4; q++) {
            #pragma unroll
            for (int o = 1; o <= 2; o <<= 1) {
                lAll[q] += __shfl_xor_sync(0xffffffffu, lAll[q], o);
                lHS[q]  += __shfl_xor_sync(0xffffffffu, lHS[q],  o);
                lHC[q]  += __shfl_xor_sync(0xffffffffu, lHC[q],  o);
                lPS[q]  += __shfl_xor_sync(0xffffffffu, lPS[q],  o);
                lPC[q]  += __shfl_xor_sync(0xffffffffu, lPC[q],  o);
            }
            if (tq == 0) {
                atomicAdd(&g_all[rows[q]],   lAll[q]);
                atomicAdd(&g_hsum[rows[q]],  lHS[q]);
                atomicAdd(&g_hcnt[rows[q]],  lHC[q]);
                atomicAdd(&g_pbsum[rows[q]], lPS[q]);
                atomicAdd(&g_pbcnt[rows[q]], lPC[q]);
            }
        }
    }

    // ---------------- last-block-done combine (replaces k_final launch) ----------------
    __shared__ unsigned int s_last;
    __syncthreads();                       // all threads of this block done issuing stores
    __threadfence();                       // make this block's writes globally visible
    if (threadIdx.x == 0) {
        unsigned int ticket = atomicAdd(&g_cnt, 1u);
        s_last = (ticket == NBLK - 1u) ? 1u : 0u;
    }
    __syncthreads();
    if (s_last) {
        int t = threadIdx.x;               // 256 threads, 2 samples each
        float part = 0.f;
        #pragma unroll
        for (int rep = 0; rep < 2; rep++) {
            int i = t + rep*256;
            int lab = labels[i];
            int wp = (memptr[lab] + g_rank[i]) % MEMSZ;
            if (wp < 64) g_ov[lab*64 + wp] = 0;   // restore all-zero invariant

            float osum = 0.f;
            #pragma unroll 10
            for (int k = 0; k < KPOS; k++) osum += g_own[k*BATCHN + i];
            float ps = g_pbsum[i] + osum;
            float pc = g_pbcnt[i] + (float)KPOS;
            float pl = -ps / pc;
            float hc = g_hcnt[i];
            float nl = (hc > 0.f) ? (g_hsum[i] / fmaxf(hc, 1.f))
                                  : (g_all[i] / ((float)(NCLS - 1) * (float)KNEG));
            part += pl + nl;
        }
        // block-reduce 256 partials
        __shared__ float red[8];
        for (int o = 16; o; o >>= 1) part += __shfl_xor_sync(0xffffffffu, part, o);
        if ((t & 31) == 0) red[t >> 5] = part;
        __syncthreads();
        if (t == 0) {
            float tot = 0.f;
            #pragma unroll
            for (int w = 0; w < 8; w++) tot += red[w];
            out[0] = tot / (float)BATCHN;
            g_cnt = 0u;                    // reset ticket for next graph replay
        }
    }
}

// ================= launch =================
extern "C" void kernel_launch(void* const* d_in, const int* in_sizes, int n_in,
                              void* d_out, int out_size)
{
    const float* feat   = (const float*)d_in[0];
    const int*   labels = (const int*)  d_in[1];
    const float* bank   = (const float*)d_in[2];
    const int*   mptr   = (const int*)  d_in[3];
    float* out = (float*)d_out;

    cudaFuncSetAttribute(k_gemm, cudaFuncAttributeMaxDynamicSharedMemorySize, SMEM_TOTAL);

    k_norm<<<BATCHN + 1, 512>>>(feat, labels, mptr);   // block 512 = setup
    k_bmat<<<NPAD/4, 256>>>(bank);
    k_gemm<<<NBLK, 256, SMEM_TOTAL>>>(labels, bank, out, mptr);
}

// round 14
// speedup vs baseline: 1.3652x; 1.3652x over previous
#include <cuda_runtime.h>
#include <cuda_bf16.h>
#include <cstdint>

#define BATCHN 512
#define DIM    512
#define NCLS   1000
#define MEMSZ  200
#define KPOS   50
#define KNEG   20
#define INV_TEMP (1.0f/0.07f)
#define MARGIN 0.5f

#define NMEM  (NCLS*KNEG)        // 20000 neg rows (c,k)
#define NTOT  (NMEM + BATCHN)    // 20512 (+ f rows)
#define NPAD  20608              // 161 * 128
#define NGEMM 644                // 161 ntiles * 4 mtiles

// ---------------- GEMM config (MT=128, NT=128 best known) ----------------
#define MT 128
#define NT 128
#define KT 64
#define NSTAGE 3
#define SMEM_A_BYTES (MT*KT*2)   // 16384
#define SMEM_B_BYTES (NT*KT*2)   // 16384
#define SMEM_TOTAL (NSTAGE*(SMEM_A_BYTES+SMEM_B_BYTES))  // 98304

// ---------------- device scratch (no runtime alloc allowed) ----------------
__device__ __align__(256) float         g_fnorm[BATCHN*DIM];      // normalized f (fp32)
__device__ __align__(256) __nv_bfloat16 g_fb[BATCHN*DIM];         // normalized f (bf16)
__device__ __align__(256) __nv_bfloat16 g_bmat[(size_t)NPAD*DIM]; // packed B matrix (bf16) ~21MB
__device__ int   g_rank[BATCHN], g_gsz[BATCHN], g_fi[BATCHN];
// override table: 0 = none, else sample_idx+1. Statically zero-initialized;
// k_final resets the <=512 touched entries after each use (graph-replay safe).
__device__ int   g_ov[NCLS*64];
// own-class sims, TRANSPOSED layout: g_own[k*BATCHN + sample] (coalesced k_final reads)
__device__ float g_own[64*BATCHN];
__device__ float g_all[BATCHN], g_hsum[BATCHN], g_hcnt[BATCHN];
__device__ float g_pbsum[BATCHN], g_pbcnt[BATCHN];

// ================= K1: L2-normalize features + 8 parallel setup blocks =================
// blocks [0,512): normalize row i.  blocks [512,520): setup block sb = i-512,
// handling samples [sb*64, sb*64+64) with 8 partial-scan threads per sample.
__global__ void k_norm(const float* __restrict__ feat,
                       const int* __restrict__ labels,
                       const int* __restrict__ memptr)
{
    int i = blockIdx.x;
    int t = threadIdx.x;               // 512 threads

    if (i >= BATCHN) {
        int sb = i - BATCHN;           // 0..7
        __shared__ int sl[BATCHN];
        sl[t] = labels[t];
        if (t < 64) {
            int s = sb*64 + t;
            g_all[s] = 0.f; g_hsum[s] = 0.f; g_hcnt[s] = 0.f;
            g_pbsum[s] = 0.f; g_pbcnt[s] = 0.f;
        }
        __syncthreads();

        int s_loc = t >> 3;            // 0..63 sample within block
        int part  = t & 7;             // 0..7 partial scanner
        int s = sb*64 + s_loc;
        int lab = sl[s];
        int r = 0, g = 0, first = BATCHN;
        int j0 = part*64;
        #pragma unroll 8
        for (int j = j0; j < j0 + 64; j++) {
            bool same = (sl[j] == lab);
            g += same;
            r += (same && j < s);
            if (same && j < first) first = j;
        }
        // reduce the 8 partials (contiguous 8-lane groups within a warp)
        #pragma unroll
        for (int o = 1; o < 8; o <<= 1) {
            r += __shfl_xor_sync(0xffffffffu, r, o);
            g += __shfl_xor_sync(0xffffffffu, g, o);
            int f2 = __shfl_xor_sync(0xffffffffu, first, o);
            first = min(first, f2);
        }
        if (part == 0) {
            g_rank[s] = r; g_gsz[s] = g; g_fi[s] = first;
            int wp = (memptr[lab] + r) % MEMSZ;
            if (wp < 64) g_ov[lab*64 + wp] = s + 1;   // +1 encoding, 0 = none
        }
        return;
    }

    // ---- normalization: one element per thread ----
    __shared__ float red[16];
    float v = feat[(size_t)i*DIM + t];
    float s = v*v;
    for (int o = 16; o; o >>= 1) s += __shfl_xor_sync(0xffffffffu, s, o);
    if ((t & 31) == 0) red[t >> 5] = s;
    __syncthreads();
    float tot = 0.f;
    #pragma unroll
    for (int w = 0; w < 16; w++) tot += red[w];
    float inv = 1.0f / fmaxf(sqrtf(tot), 1e-12f);
    float nv = v * inv;
    g_fnorm[(size_t)i*DIM + t] = nv;
    g_fb[(size_t)i*DIM + t]    = __float2bfloat16(nv);
}

// ================= K2: materialize packed bf16 B matrix (vectorized) =================
// 4 rows per block; 64 threads per row; each thread: 8 floats -> one 16B store
__global__ void k_bmat(const float* __restrict__ bank)
{
    int t  = threadIdx.x;              // 256
    int lr = t >> 6, l = t & 63;
    int r  = blockIdx.x*4 + lr;        // NPAD/4 blocks

    const float* src = nullptr;
    if (r < NMEM) {
        int c = r / KNEG, k = r - c*KNEG;
        int o = g_ov[c*64 + k];
        src = (o > 0) ? (g_fnorm + (size_t)(o - 1)*DIM)
                      : (bank + ((size_t)c*MEMSZ + k)*DIM);
    } else if (r < NTOT) {
        src = g_fnorm + (size_t)(r - NMEM)*DIM;
    }

    float4 v0, v1;
    if (src) {
        v0 = ((const float4*)src)[2*l];
        v1 = ((const float4*)src)[2*l + 1];
    } else {
        v0 = make_float4(0.f,0.f,0.f,0.f);
        v1 = v0;
    }
    __nv_bfloat162 b0 = __floats2bfloat162_rn(v0.x, v0.y);
    __nv_bfloat162 b1 = __floats2bfloat162_rn(v0.z, v0.w);
    __nv_bfloat162 b2 = __floats2bfloat162_rn(v1.x, v1.y);
    __nv_bfloat162 b3 = __floats2bfloat162_rn(v1.z, v1.w);
    uint4 pack;
    pack.x = *(const uint32_t*)&b0;
    pack.y = *(const uint32_t*)&b1;
    pack.z = *(const uint32_t*)&b2;
    pack.w = *(const uint32_t*)&b3;
    ((uint4*)(g_bmat + (size_t)r*DIM))[l] = pack;
}

// ================= K3: fused GEMM + masked reductions + own-GEMV tail blocks =================
__device__ __forceinline__ void mma_bf16(float c[4], const uint32_t a[4], uint32_t b0, uint32_t b1)
{
    asm volatile(
        "mma.sync.aligned.m16n8k16.row.col.f32.bf16.bf16.f32 "
        "{%0,%1,%2,%3},{%4,%5,%6,%7},{%8,%9},{%0,%1,%2,%3};"
        : "+f"(c[0]), "+f"(c[1]), "+f"(c[2]), "+f"(c[3])
        : "r"(a[0]), "r"(a[1]), "r"(a[2]), "r"(a[3]), "r"(b0), "r"(b1));
}

extern "C" __global__ void __launch_bounds__(256, 2)
k_gemm(const int* __restrict__ labels, const float* __restrict__ bank)
{
    extern __shared__ char smem[];
    const int bid = blockIdx.x;

    // ---------- own-GEMV tail blocks: bid in [NGEMM, NGEMM+512) ----------
    if (bid >= NGEMM) {
        int i = bid - NGEMM;              // 0..511
        int t = threadIdx.x;              // 256
        float4* fsh = (float4*)smem;      // 2 KB scratch
        for (int j = t; j < DIM/4; j += 256)
            fsh[j] = ((const float4*)(g_fnorm + (size_t)i*DIM))[j];
        __syncthreads();
        int lab = labels[i];
        int w = t >> 5, lane = t & 31;    // 8 warps
        for (int k = KNEG + w; k < KPOS; k += 8) {
            int o = g_ov[lab*64 + k];
            const float4* row = (const float4*)((o > 0)
                ? (g_fnorm + (size_t)(o - 1)*DIM)
                : (bank + ((size_t)lab*MEMSZ + k)*DIM));
            float s = 0.f;
            #pragma unroll
            for (int c = 0; c < 4; c++) {
                float4 a = row[lane + c*32], b = fsh[lane + c*32];
                s += a.x*b.x + a.y*b.y + a.z*b.z + a.w*b.w;
            }
            for (int off = 16; off; off >>= 1) s += __shfl_xor_sync(0xffffffffu, s, off);
            if (lane == 0) g_own[k*BATCHN + i] = s * INV_TEMP;
        }
        return;
    }

    // ---------- GEMM blocks: bid = ntile*4 + mtile (mtile-adjacent for L2 reuse) ----------
    uint32_t saA = (uint32_t)__cvta_generic_to_shared(smem);
    uint32_t saB = saA + NSTAGE*SMEM_A_BYTES;

    const int t     = threadIdx.x;    // 256
    const int ntile = bid >> 2;       // 161
    const int mtile = bid & 3;        // 4
    const int mbase = mtile*MT, nbase = ntile*NT;
    const int wid = t >> 5, lane = t & 31;
    const int wm = wid >> 1, wn = wid & 1;      // 4 x 2 warp grid, warp tile 32x64

    // ---- cp.async staging (bf16 everywhere, 16B chunks) ----
    auto loadA = [&](int stage, int kbase) {
        #pragma unroll
        for (int i = 0; i < 4; i++) {
            int idx = t + i*256;                 // 1024 chunks = 128 rows x 8
            int row = idx >> 3, cc = idx & 7;
            const void* g = g_fb + (size_t)(mbase + row)*DIM + kbase + cc*8;
            uint32_t d = saA + stage*SMEM_A_BYTES + row*128 + ((cc*16) ^ ((row & 7) << 4));
            asm volatile("cp.async.cg.shared.global [%0], [%1], 16;" :: "r"(d), "l"(g));
        }
    };
    auto loadB = [&](int stage, int kbase) {
        #pragma unroll
        for (int i = 0; i < 4; i++) {
            int idx = t + i*256;                 // 1024 chunks
            int row = idx >> 3, cc = idx & 7;
            const void* g = g_bmat + (size_t)(nbase + row)*DIM + kbase + cc*8;
            uint32_t d = saB + stage*SMEM_B_BYTES + row*128 + ((cc*16) ^ ((row & 7) << 4));
            asm volatile("cp.async.cg.shared.global [%0], [%1], 16;" :: "r"(d), "l"(g));
        }
    };

    float acc[2][8][4];
    #pragma unroll
    for (int a = 0; a < 2; a++)
        #pragma unroll
        for (int b = 0; b < 8; b++)
            #pragma unroll
            for (int c = 0; c < 4; c++) acc[a][b][c] = 0.f;

    loadA(0, 0);  loadB(0, 0);  asm volatile("cp.async.commit_group;" ::: "memory");
    loadA(1, KT); loadB(1, KT); asm volatile("cp.async.commit_group;" ::: "memory");

    // ldmatrix lane coordinates
    const int a_row  = wm*32 + (lane & 15);            // + mi*16
    const int a_xor  = (a_row & 7) << 4;
    const int a_c8b  = ((lane >> 4) & 1) * 16;         // bytes (8 bf16)
    const int b_rin  = (lane & 7) + (((lane >> 4) & 1) << 3);
    const int b_c8b  = ((lane >> 3) & 1) * 16;         // bytes

    const int NS = DIM / KT;  // 8
    for (int ks = 0; ks < NS; ks++) {
        if (ks < NS - 1) asm volatile("cp.async.wait_group 1;" ::: "memory");
        else             asm volatile("cp.async.wait_group 0;" ::: "memory");
        __syncthreads();

        if (ks + 2 < NS) {
            int st = (ks + 2) % NSTAGE;
            loadA(st, (ks + 2)*KT); loadB(st, (ks + 2)*KT);
            asm volatile("cp.async.commit_group;" ::: "memory");
        }

        uint32_t sa = saA + (ks % NSTAGE)*SMEM_A_BYTES;
        uint32_t sb = saB + (ks % NSTAGE)*SMEM_B_BYTES;

        #pragma unroll
        for (int kk = 0; kk < 4; kk++) {
            uint32_t afr[2][4];
            uint32_t bfr[4][4];
            #pragma unroll
            for (int mi = 0; mi < 2; mi++) {
                uint32_t addr = sa + (a_row + mi*16)*128 + ((kk*32 + a_c8b) ^ a_xor);
                asm volatile("ldmatrix.sync.aligned.m8n8.x4.shared.b16 {%0,%1,%2,%3}, [%4];"
                    : "=r"(afr[mi][0]), "=r"(afr[mi][1]), "=r"(afr[mi][2]), "=r"(afr[mi][3])
                    : "r"(addr));
            }
            #pragma unroll
            for (int np = 0; np < 4; np++) {
                int nrow = wn*64 + np*16 + b_rin;
                uint32_t baddr = sb + nrow*128 + ((kk*32 + b_c8b) ^ ((nrow & 7) << 4));
                asm volatile("ldmatrix.sync.aligned.m8n8.x4.shared.b16 {%0,%1,%2,%3}, [%4];"
                    : "=r"(bfr[np][0]), "=r"(bfr[np][1]), "=r"(bfr[np][2]), "=r"(bfr[np][3])
                    : "r"(baddr));
            }
            #pragma unroll
            for (int np = 0; np < 4; np++) {
                #pragma unroll
                for (int mi = 0; mi < 2; mi++) {
                    mma_bf16(acc[mi][2*np],   afr[mi], bfr[np][0], bfr[np][1]);
                    mma_bf16(acc[mi][2*np+1], afr[mi], bfr[np][2], bfr[np][3]);
                }
            }
        }
    }

    // ---------------- fused epilogue ----------------
    const int gid = lane >> 2, tq = lane & 3;
    int rows[4]; int lab[4]; int fi_[4]; int gsz_[4];
    #pragma unroll
    for (int mi = 0; mi < 2; mi++) {
        int r0 = mbase + wm*32 + mi*16 + gid;
        rows[2*mi] = r0; rows[2*mi+1] = r0 + 8;
    }
    #pragma unroll
    for (int q = 0; q < 4; q++) {
        lab[q]  = labels[rows[q]];
        fi_[q]  = g_fi[rows[q]];
        gsz_[q] = g_gsz[rows[q]];
    }

    float lAll[4] = {0,0,0,0}, lHS[4] = {0,0,0,0}, lHC[4] = {0,0,0,0};
    float lPS[4] = {0,0,0,0}, lPC[4] = {0,0,0,0};

    #pragma unroll
    for (int nf = 0; nf < 8; nf++) {
        int ncol0 = nbase + wn*64 + nf*8 + tq*2;
        #pragma unroll
        for (int cc = 0; cc < 2; cc++) {
            int r = ncol0 + cc;
            int type, cC = 0, kK = 0, lj = 0, rj = 0;
            if (r < NMEM)      { type = 0; cC = r / KNEG; kK = r - cC*KNEG; }
            else if (r < NTOT) { type = 1; int j = r - NMEM; lj = labels[j]; rj = g_rank[j]; }
            else               { type = 2; }
            #pragma unroll
            for (int q = 0; q < 4; q++) {
                float s = acc[q >> 1][nf][(q & 1)*2 + cc] * INV_TEMP;
                if (type == 0) {
                    if (cC == lab[q]) {
                        g_own[kK*BATCHN + rows[q]] = s;  // unique writer, covers all k<20
                    } else {
                        lAll[q] += s;
                        if (s > MARGIN) { lHS[q] += s; lHC[q] += 1.f; }
                    }
                } else if (type == 1) {
                    if (lj == lab[q] && rj != fi_[q] && gsz_[q] > 1) {
                        lPS[q] += s; lPC[q] += 1.f;
                    }
                }
            }
        }
    }

    // quad reduction (lanes sharing the same rows) + global atomics
    #pragma unroll
    for (int q = 0; q < 4; q++) {
        #pragma unroll
        for (int o = 1; o <= 2; o <<= 1) {
            lAll[q] += __shfl_xor_sync(0xffffffffu, lAll[q], o);
            lHS[q]  += __shfl_xor_sync(0xffffffffu, lHS[q],  o);
            lHC[q]  += __shfl_xor_sync(0xffffffffu, lHC[q],  o);
            lPS[q]  += __shfl_xor_sync(0xffffffffu, lPS[q],  o);
            lPC[q]  += __shfl_xor_sync(0xffffffffu, lPC[q],  o);
        }
        if (tq == 0) {
            atomicAdd(&g_all[rows[q]],   lAll[q]);
            atomicAdd(&g_hsum[rows[q]],  lHS[q]);
            atomicAdd(&g_hcnt[rows[q]],  lHC[q]);
            atomicAdd(&g_pbsum[rows[q]], lPS[q]);
            atomicAdd(&g_pbcnt[rows[q]], lPC[q]);
        }
    }
}

// ================= K5: combine + mean (+ reset override table for next replay) =================
__global__ void k_final(float* __restrict__ out,
                        const int* __restrict__ labels,
                        const int* __restrict__ memptr)
{
    int t = threadIdx.x;              // 512

    // reset the <=512 touched g_ov entries (restores all-zero invariant for replay)
    {
        int lab = labels[t];
        int wp = (memptr[lab] + g_rank[t]) % MEMSZ;
        if (wp < 64) g_ov[lab*64 + wp] = 0;
    }

    // coalesced own-sum: g_own is [k][sample]
    float osum = 0.f;
    #pragma unroll 10
    for (int k = 0; k < KPOS; k++) osum += g_own[k*BATCHN + t];
    float ps = g_pbsum[t] + osum;
    float pc = g_pbcnt[t] + (float)KPOS;
    float pl = -ps / pc;
    float hc = g_hcnt[t];
    float nl = (hc > 0.f) ? (g_hsum[t] / fmaxf(hc, 1.f))
                          : (g_all[t] / ((float)(NCLS - 1) * (float)KNEG));
    float v = pl + nl;

    __shared__ float red[16];
    for (int o = 16; o; o >>= 1) v += __shfl_xor_sync(0xffffffffu, v, o);
    if ((t & 31) == 0) red[t >> 5] = v;
    __syncthreads();
    if (t < 32) {
        float x = (t < 16) ? red[t] : 0.f;
        for (int o = 8; o; o >>= 1) x += __shfl_xor_sync(0xffffffffu, x, o);
        if (t == 0) out[0] = x / (float)BATCHN;
    }
}

// ================= launch =================
extern "C" void kernel_launch(void* const* d_in, const int* in_sizes, int n_in,
                              void* d_out, int out_size)
{
    const float* feat   = (const float*)d_in[0];
    const int*   labels = (const int*)  d_in[1];
    const float* bank   = (const float*)d_in[2];
    const int*   mptr   = (const int*)  d_in[3];
    float* out = (float*)d_out;

    cudaFuncSetAttribute(k_gemm, cudaFuncAttributeMaxDynamicSharedMemorySize, SMEM_TOTAL);

    k_norm<<<BATCHN + 8, 512>>>(feat, labels, mptr);   // blocks 512..519 = parallel setup
    k_bmat<<<NPAD/4, 256>>>(bank);
    k_gemm<<<NGEMM + BATCHN, 256, SMEM_TOTAL>>>(labels, bank);
    k_final<<<1, 512>>>(out, labels, mptr);
}

// round 15
// speedup vs baseline: 1.4476x; 1.0604x over previous
#include <cuda_runtime.h>
#include <cuda_bf16.h>
#include <cstdint>

#define BATCHN 512
#define DIM    512
#define NCLS   1000
#define MEMSZ  200
#define KPOS   50
#define KNEG   20
#define INV_TEMP (1.0f/0.07f)
#define MARGIN 0.5f

#define NMEM  (NCLS*KNEG)        // 20000 neg rows (c,k)
#define NTOT  (NMEM + BATCHN)    // 20512 (+ f rows)
#define NPAD  20608              // 161 * 128
#define NGEMM 644                // 161 ntiles * 4 mtiles

// ---------------- GEMM config (MT=128, NT=128 best known) ----------------
#define MT 128
#define NT 128
#define KT 64
#define NSTAGE 3
#define SMEM_A_BYTES (MT*KT*2)   // 16384
#define SMEM_B_BYTES (NT*KT*2)   // 16384
#define SMEM_TOTAL (NSTAGE*(SMEM_A_BYTES+SMEM_B_BYTES))  // 98304

// ---------------- device scratch (no runtime alloc allowed) ----------------
__device__ __align__(256) float         g_fnorm[BATCHN*DIM];      // normalized f (fp32)
__device__ __align__(256) __nv_bfloat16 g_fb[BATCHN*DIM];         // normalized f (bf16)
__device__ __align__(256) __nv_bfloat16 g_bmat[(size_t)NPAD*DIM]; // packed B matrix (bf16) ~21MB
__device__ int   g_rank[BATCHN], g_gsz[BATCHN], g_fi[BATCHN];
// override table: 0 = none, else sample_idx+1. Statically zero-initialized;
// k_final resets the <=512 touched entries after each use (graph-replay safe).
__device__ int   g_ov[NCLS*64];
// NOTE: g_own removed — all own-class sims accumulate directly into g_pbsum.
__device__ float g_all[BATCHN], g_hsum[BATCHN], g_hcnt[BATCHN];
__device__ float g_pbsum[BATCHN], g_pbcnt[BATCHN];

// ================= K1: L2-normalize features + 8 parallel setup blocks =================
// blocks [0,512): normalize row i.  blocks [512,520): setup block sb = i-512,
// handling samples [sb*64, sb*64+64) with 8 partial-scan threads per sample.
__global__ void k_norm(const float* __restrict__ feat,
                       const int* __restrict__ labels,
                       const int* __restrict__ memptr)
{
    int i = blockIdx.x;
    int t = threadIdx.x;               // 512 threads

    if (i >= BATCHN) {
        int sb = i - BATCHN;           // 0..7
        __shared__ int sl[BATCHN];
        sl[t] = labels[t];
        if (t < 64) {
            int s = sb*64 + t;
            g_all[s] = 0.f; g_hsum[s] = 0.f; g_hcnt[s] = 0.f;
            g_pbsum[s] = 0.f; g_pbcnt[s] = 0.f;
        }
        __syncthreads();

        int s_loc = t >> 3;            // 0..63 sample within block
        int part  = t & 7;             // 0..7 partial scanner
        int s = sb*64 + s_loc;
        int lab = sl[s];
        int r = 0, g = 0, first = BATCHN;
        int j0 = part*64;
        #pragma unroll 8
        for (int j = j0; j < j0 + 64; j++) {
            bool same = (sl[j] == lab);
            g += same;
            r += (same && j < s);
            if (same && j < first) first = j;
        }
        // reduce the 8 partials (contiguous 8-lane groups within a warp)
        #pragma unroll
        for (int o = 1; o < 8; o <<= 1) {
            r += __shfl_xor_sync(0xffffffffu, r, o);
            g += __shfl_xor_sync(0xffffffffu, g, o);
            int f2 = __shfl_xor_sync(0xffffffffu, first, o);
            first = min(first, f2);
        }
        if (part == 0) {
            g_rank[s] = r; g_gsz[s] = g; g_fi[s] = first;
            int wp = (memptr[lab] + r) % MEMSZ;
            if (wp < 64) g_ov[lab*64 + wp] = s + 1;   // +1 encoding, 0 = none
        }
        return;
    }

    // ---- normalization: one element per thread ----
    __shared__ float red[16];
    float v = feat[(size_t)i*DIM + t];
    float s = v*v;
    for (int o = 16; o; o >>= 1) s += __shfl_xor_sync(0xffffffffu, s, o);
    if ((t & 31) == 0) red[t >> 5] = s;
    __syncthreads();
    float tot = 0.f;
    #pragma unroll
    for (int w = 0; w < 16; w++) tot += red[w];
    float inv = 1.0f / fmaxf(sqrtf(tot), 1e-12f);
    float nv = v * inv;
    g_fnorm[(size_t)i*DIM + t] = nv;
    g_fb[(size_t)i*DIM + t]    = __float2bfloat16(nv);
}

// ================= K2: materialize packed bf16 B matrix (vectorized) =================
// 4 rows per block; 64 threads per row; each thread: 8 floats -> one 16B store
__global__ void k_bmat(const float* __restrict__ bank)
{
    int t  = threadIdx.x;              // 256
    int lr = t >> 6, l = t & 63;
    int r  = blockIdx.x*4 + lr;        // NPAD/4 blocks

    const float* src = nullptr;
    if (r < NMEM) {
        int c = r / KNEG, k = r - c*KNEG;
        int o = g_ov[c*64 + k];
        src = (o > 0) ? (g_fnorm + (size_t)(o - 1)*DIM)
                      : (bank + ((size_t)c*MEMSZ + k)*DIM);
    } else if (r < NTOT) {
        src = g_fnorm + (size_t)(r - NMEM)*DIM;
    }

    float4 v0, v1;
    if (src) {
        v0 = ((const float4*)src)[2*l];
        v1 = ((const float4*)src)[2*l + 1];
    } else {
        v0 = make_float4(0.f,0.f,0.f,0.f);
        v1 = v0;
    }
    __nv_bfloat162 b0 = __floats2bfloat162_rn(v0.x, v0.y);
    __nv_bfloat162 b1 = __floats2bfloat162_rn(v0.z, v0.w);
    __nv_bfloat162 b2 = __floats2bfloat162_rn(v1.x, v1.y);
    __nv_bfloat162 b3 = __floats2bfloat162_rn(v1.z, v1.w);
    uint4 pack;
    pack.x = *(const uint32_t*)&b0;
    pack.y = *(const uint32_t*)&b1;
    pack.z = *(const uint32_t*)&b2;
    pack.w = *(const uint32_t*)&b3;
    ((uint4*)(g_bmat + (size_t)r*DIM))[l] = pack;
}

// ================= K3: fused GEMM + masked reductions + own-GEMV tail blocks =================
__device__ __forceinline__ void mma_bf16(float c[4], const uint32_t a[4], uint32_t b0, uint32_t b1)
{
    asm volatile(
        "mma.sync.aligned.m16n8k16.row.col.f32.bf16.bf16.f32 "
        "{%0,%1,%2,%3},{%4,%5,%6,%7},{%8,%9},{%0,%1,%2,%3};"
        : "+f"(c[0]), "+f"(c[1]), "+f"(c[2]), "+f"(c[3])
        : "r"(a[0]), "r"(a[1]), "r"(a[2]), "r"(a[3]), "r"(b0), "r"(b1));
}

extern "C" __global__ void __launch_bounds__(256, 2)
k_gemm(const int* __restrict__ labels, const float* __restrict__ bank)
{
    extern __shared__ char smem[];
    const int bid = blockIdx.x;

    // ---------- own-GEMV tail blocks: bid in [NGEMM, NGEMM+512) ----------
    if (bid >= NGEMM) {
        int i = bid - NGEMM;              // 0..511
        int t = threadIdx.x;              // 256
        float4* fsh = (float4*)smem;      // 2 KB scratch
        for (int j = t; j < DIM/4; j += 256)
            fsh[j] = ((const float4*)(g_fnorm + (size_t)i*DIM))[j];
        __syncthreads();
        int lab = labels[i];
        int w = t >> 5, lane = t & 31;    // 8 warps
        float wsum = 0.f;
        for (int k = KNEG + w; k < KPOS; k += 8) {
            int o = g_ov[lab*64 + k];
            const float4* row = (const float4*)((o > 0)
                ? (g_fnorm + (size_t)(o - 1)*DIM)
                : (bank + ((size_t)lab*MEMSZ + k)*DIM));
            float s = 0.f;
            #pragma unroll
            for (int c = 0; c < 4; c++) {
                float4 a = row[lane + c*32], b = fsh[lane + c*32];
                s += a.x*b.x + a.y*b.y + a.z*b.z + a.w*b.w;
            }
            for (int off = 16; off; off >>= 1) s += __shfl_xor_sync(0xffffffffu, s, off);
            wsum += s;
        }
        if (lane == 0) atomicAdd(&g_pbsum[i], wsum * INV_TEMP);
        return;
    }

    // ---------- GEMM blocks: bid = ntile*4 + mtile (mtile-adjacent for L2 reuse) ----------
    uint32_t saA = (uint32_t)__cvta_generic_to_shared(smem);
    uint32_t saB = saA + NSTAGE*SMEM_A_BYTES;

    const int t     = threadIdx.x;    // 256
    const int ntile = bid >> 2;       // 161
    const int mtile = bid & 3;        // 4
    const int mbase = mtile*MT, nbase = ntile*NT;
    const int wid = t >> 5, lane = t & 31;
    const int wm = wid >> 1, wn = wid & 1;      // 4 x 2 warp grid, warp tile 32x64

    // ---- cp.async staging (bf16 everywhere, 16B chunks) ----
    auto loadA = [&](int stage, int kbase) {
        #pragma unroll
        for (int i = 0; i < 4; i++) {
            int idx = t + i*256;                 // 1024 chunks = 128 rows x 8
            int row = idx >> 3, cc = idx & 7;
            const void* g = g_fb + (size_t)(mbase + row)*DIM + kbase + cc*8;
            uint32_t d = saA + stage*SMEM_A_BYTES + row*128 + ((cc*16) ^ ((row & 7) << 4));
            asm volatile("cp.async.cg.shared.global [%0], [%1], 16;" :: "r"(d), "l"(g));
        }
    };
    auto loadB = [&](int stage, int kbase) {
        #pragma unroll
        for (int i = 0; i < 4; i++) {
            int idx = t + i*256;                 // 1024 chunks
            int row = idx >> 3, cc = idx & 7;
            const void* g = g_bmat + (size_t)(nbase + row)*DIM + kbase + cc*8;
            uint32_t d = saB + stage*SMEM_B_BYTES + row*128 + ((cc*16) ^ ((row & 7) << 4));
            asm volatile("cp.async.cg.shared.global [%0], [%1], 16;" :: "r"(d), "l"(g));
        }
    };

    float acc[2][8][4];
    #pragma unroll
    for (int a = 0; a < 2; a++)
        #pragma unroll
        for (int b = 0; b < 8; b++)
            #pragma unroll
            for (int c = 0; c < 4; c++) acc[a][b][c] = 0.f;

    loadA(0, 0);  loadB(0, 0);  asm volatile("cp.async.commit_group;" ::: "memory");
    loadA(1, KT); loadB(1, KT); asm volatile("cp.async.commit_group;" ::: "memory");

    // ldmatrix lane coordinates
    const int a_row  = wm*32 + (lane & 15);            // + mi*16
    const int a_xor  = (a_row & 7) << 4;
    const int a_c8b  = ((lane >> 4) & 1) * 16;         // bytes (8 bf16)
    const int b_rin  = (lane & 7) + (((lane >> 4) & 1) << 3);
    const int b_c8b  = ((lane >> 3) & 1) * 16;         // bytes

    const int NS = DIM / KT;  // 8
    for (int ks = 0; ks < NS; ks++) {
        if (ks < NS - 1) asm volatile("cp.async.wait_group 1;" ::: "memory");
        else             asm volatile("cp.async.wait_group 0;" ::: "memory");
        __syncthreads();

        if (ks + 2 < NS) {
            int st = (ks + 2) % NSTAGE;
            loadA(st, (ks + 2)*KT); loadB(st, (ks + 2)*KT);
            asm volatile("cp.async.commit_group;" ::: "memory");
        }

        uint32_t sa = saA + (ks % NSTAGE)*SMEM_A_BYTES;
        uint32_t sb = saB + (ks % NSTAGE)*SMEM_B_BYTES;

        #pragma unroll
        for (int kk = 0; kk < 4; kk++) {
            uint32_t afr[2][4];
            uint32_t bfr[4][4];
            #pragma unroll
            for (int mi = 0; mi < 2; mi++) {
                uint32_t addr = sa + (a_row + mi*16)*128 + ((kk*32 + a_c8b) ^ a_xor);
                asm volatile("ldmatrix.sync.aligned.m8n8.x4.shared.b16 {%0,%1,%2,%3}, [%4];"
                    : "=r"(afr[mi][0]), "=r"(afr[mi][1]), "=r"(afr[mi][2]), "=r"(afr[mi][3])
                    : "r"(addr));
            }
            #pragma unroll
            for (int np = 0; np < 4; np++) {
                int nrow = wn*64 + np*16 + b_rin;
                uint32_t baddr = sb + nrow*128 + ((kk*32 + b_c8b) ^ ((nrow & 7) << 4));
                asm volatile("ldmatrix.sync.aligned.m8n8.x4.shared.b16 {%0,%1,%2,%3}, [%4];"
                    : "=r"(bfr[np][0]), "=r"(bfr[np][1]), "=r"(bfr[np][2]), "=r"(bfr[np][3])
                    : "r"(baddr));
            }
            #pragma unroll
            for (int np = 0; np < 4; np++) {
                #pragma unroll
                for (int mi = 0; mi < 2; mi++) {
                    mma_bf16(acc[mi][2*np],   afr[mi], bfr[np][0], bfr[np][1]);
                    mma_bf16(acc[mi][2*np+1], afr[mi], bfr[np][2], bfr[np][3]);
                }
            }
        }
    }

    // ---------------- fused epilogue ----------------
    const int gid = lane >> 2, tq = lane & 3;
    int rows[4]; int lab[4]; int fi_[4]; int gsz_[4];
    #pragma unroll
    for (int mi = 0; mi < 2; mi++) {
        int r0 = mbase + wm*32 + mi*16 + gid;
        rows[2*mi] = r0; rows[2*mi+1] = r0 + 8;
    }
    #pragma unroll
    for (int q = 0; q < 4; q++) {
        lab[q]  = labels[rows[q]];
        fi_[q]  = g_fi[rows[q]];
        gsz_[q] = g_gsz[rows[q]];
    }

    float lAll[4] = {0,0,0,0}, lHS[4] = {0,0,0,0}, lHC[4] = {0,0,0,0};
    float lPS[4] = {0,0,0,0}, lPC[4] = {0,0,0,0};

    #pragma unroll
    for (int nf = 0; nf < 8; nf++) {
        int ncol0 = nbase + wn*64 + nf*8 + tq*2;
        #pragma unroll
        for (int cc = 0; cc < 2; cc++) {
            int r = ncol0 + cc;
            int type, cC = 0, lj = 0, rj = 0;
            if (r < NMEM)      { type = 0; cC = r / KNEG; }
            else if (r < NTOT) { type = 1; int j = r - NMEM; lj = labels[j]; rj = g_rank[j]; }
            else               { type = 2; }
            #pragma unroll
            for (int q = 0; q < 4; q++) {
                float s = acc[q >> 1][nf][(q & 1)*2 + cc] * INV_TEMP;
                if (type == 0) {
                    if (cC == lab[q]) {
                        lPS[q] += s;                     // own-class k<20: part of pos_sum
                    } else {
                        lAll[q] += s;
                        if (s > MARGIN) { lHS[q] += s; lHC[q] += 1.f; }
                    }
                } else if (type == 1) {
                    if (lj == lab[q] && rj != fi_[q] && gsz_[q] > 1) {
                        lPS[q] += s; lPC[q] += 1.f;
                    }
                }
            }
        }
    }

    // quad reduction (lanes sharing the same rows) + global atomics
    #pragma unroll
    for (int q = 0; q < 4; q++) {
        #pragma unroll
        for (int o = 1; o <= 2; o <<= 1) {
            lAll[q] += __shfl_xor_sync(0xffffffffu, lAll[q], o);
            lHS[q]  += __shfl_xor_sync(0xffffffffu, lHS[q],  o);
            lHC[q]  += __shfl_xor_sync(0xffffffffu, lHC[q],  o);
            lPS[q]  += __shfl_xor_sync(0xffffffffu, lPS[q],  o);
            lPC[q]  += __shfl_xor_sync(0xffffffffu, lPC[q],  o);
        }
        if (tq == 0) {
            atomicAdd(&g_all[rows[q]],   lAll[q]);
            atomicAdd(&g_hsum[rows[q]],  lHS[q]);
            atomicAdd(&g_hcnt[rows[q]],  lHC[q]);
            atomicAdd(&g_pbsum[rows[q]], lPS[q]);
            atomicAdd(&g_pbcnt[rows[q]], lPC[q]);
        }
    }
}

// ================= K5: combine + mean (+ reset override table for next replay) =================
__global__ void k_final(float* __restrict__ out,
                        const int* __restrict__ labels,
                        const int* __restrict__ memptr)
{
    int t = threadIdx.x;              // 512

    // reset the <=512 touched g_ov entries (restores all-zero invariant for replay)
    {
        int lab = labels[t];
        int wp = (memptr[lab] + g_rank[t]) % MEMSZ;
        if (wp < 64) g_ov[lab*64 + wp] = 0;
    }

    float ps = g_pbsum[t];            // already includes all 50 own-class sims
    float pc = g_pbcnt[t] + (float)KPOS;
    float pl = -ps / pc;
    float hc = g_hcnt[t];
    float nl = (hc > 0.f) ? (g_hsum[t] / fmaxf(hc, 1.f))
                          : (g_all[t] / ((float)(NCLS - 1) * (float)KNEG));
    float v = pl + nl;

    __shared__ float red[16];
    for (int o = 16; o; o >>= 1) v += __shfl_xor_sync(0xffffffffu, v, o);
    if ((t & 31) == 0) red[t >> 5] = v;
    __syncthreads();
    if (t < 32) {
        float x = (t < 16) ? red[t] : 0.f;
        for (int o = 8; o; o >>= 1) x += __shfl_xor_sync(0xffffffffu, x, o);
        if (t == 0) out[0] = x / (float)BATCHN;
    }
}

// ================= launch =================
extern "C" void kernel_launch(void* const* d_in, const int* in_sizes, int n_in,
                              void* d_out, int out_size)
{
    const float* feat   = (const float*)d_in[0];
    const int*   labels = (const int*)  d_in[1];
    const float* bank   = (const float*)d_in[2];
    const int*   mptr   = (const int*)  d_in[3];
    float* out = (float*)d_out;

    cudaFuncSetAttribute(k_gemm, cudaFuncAttributeMaxDynamicSharedMemorySize, SMEM_TOTAL);

    k_norm<<<BATCHN + 8, 512>>>(feat, labels, mptr);   // blocks 512..519 = parallel setup
    k_bmat<<<NPAD/4, 256>>>(bank);
    k_gemm<<<NGEMM + BATCHN, 256, SMEM_TOTAL>>>(labels, bank);
    k_final<<<1, 512>>>(out, labels, mptr);
}